// round 8
// baseline (speedup 1.0000x reference)
#include <cuda_runtime.h>
#include <math.h>

#define B_      256
#define T_      512
#define N_      512
#define DK_     64
#define DV_     256
#define S_      64
#define F_      64
#define SLICES_ 4
#define RPS_    128   // memory rows per slice

// -------- device scratch (static __device__ arrays; no allocations) --------
__device__ float g_keyT[DK_ * N_];                 // key_memory transposed (DK, N)
__device__ float g_wtab[(N_ + 1) * N_];            // softmax attention per concept id
__device__ float g_etab[(2 * N_ + 1) * DV_];       // sigmoid(We v + be) per interaction id
__device__ float g_atab[(2 * N_ + 1) * DV_];       // tanh(Wa v + ba)   per interaction id
__device__ float g_qc[(N_ + 1) * S_];              // W1[:,DV:] @ q + b1 per concept id
__device__ float g_rpart[134217728];               // (B, T, SLICES, DV) partial reads (512MB)

// ---------------------------------------------------------------------------
// Precompute 0: transpose key_memory (N, DK) -> (DK, N)
__global__ void k_transpose(const float* __restrict__ key) {
    int idx = blockIdx.x * blockDim.x + threadIdx.x;   // 0 .. N*DK-1
    int n = idx >> 6;
    int k = idx & 63;
    g_keyT[k * N_ + n] = key[idx];
}

// Precompute 1: w_table[c][n] = softmax_n( q_c . key_memory[n] )
__global__ void k_wtab(const float* __restrict__ cemb) {
    int c = blockIdx.x;        // 0..512
    int n = threadIdx.x;       // 0..511
    __shared__ float q[DK_];
    __shared__ float red[512];
    if (n < DK_) q[n] = cemb[c * DK_ + n];
    __syncthreads();
    float acc = 0.f;
#pragma unroll
    for (int k = 0; k < DK_; k++) acc = fmaf(q[k], g_keyT[k * N_ + n], acc);
    red[n] = acc; __syncthreads();
    for (int s = 256; s > 0; s >>= 1) { if (n < s) red[n] = fmaxf(red[n], red[n + s]); __syncthreads(); }
    float mx = red[0]; __syncthreads();
    float e = expf(acc - mx);
    red[n] = e; __syncthreads();
    for (int s = 256; s > 0; s >>= 1) { if (n < s) red[n] += red[n + s]; __syncthreads(); }
    g_wtab[c * N_ + n] = e / red[0];
}

// Precompute 2: erase/add tables per interaction id (GEMV batched over 16 ids/block)
#define IPB 16
__global__ void k_eatab(const float* __restrict__ iemb,
                        const float* __restrict__ We, const float* __restrict__ be,
                        const float* __restrict__ Wa, const float* __restrict__ ba) {
    int i0 = blockIdx.x * IPB;
    int d = threadIdx.x;                 // 0..255 output dim
    __shared__ float v[IPB][DV_];
    for (int x = threadIdx.x; x < IPB * DV_; x += blockDim.x) {
        int ii = x >> 8, k = x & 255;
        int gi = i0 + ii;
        v[ii][k] = (gi <= 2 * N_) ? iemb[gi * DV_ + k] : 0.f;
    }
    __syncthreads();
    float aE[IPB], aA[IPB];
#pragma unroll
    for (int ii = 0; ii < IPB; ii++) { aE[ii] = 0.f; aA[ii] = 0.f; }
    for (int k = 0; k < DV_; k++) {
        float we = We[d * DV_ + k];
        float wa = Wa[d * DV_ + k];
#pragma unroll
        for (int ii = 0; ii < IPB; ii++) {
            aE[ii] = fmaf(we, v[ii][k], aE[ii]);
            aA[ii] = fmaf(wa, v[ii][k], aA[ii]);
        }
    }
    float beV = be[d], baV = ba[d];
#pragma unroll
    for (int ii = 0; ii < IPB; ii++) {
        int gi = i0 + ii;
        if (gi <= 2 * N_) {
            g_etab[gi * DV_ + d] = 1.f / (1.f + expf(-(aE[ii] + beV)));
            g_atab[gi * DV_ + d] = tanhf(aA[ii] + baV);
        }
    }
}

// Precompute 3: qc[c][s] = b1[s] + sum_k W1[s][DV+k] * q_c[k]
__global__ void k_qc(const float* __restrict__ cemb, const float* __restrict__ W1,
                     const float* __restrict__ b1) {
    int c = blockIdx.x;
    int s = threadIdx.x;     // 0..63
    __shared__ float q[DK_];
    if (s < DK_) q[s] = cemb[c * DK_ + s];
    __syncthreads();
    float acc = b1[s];
#pragma unroll
    for (int k = 0; k < DK_; k++) acc = fmaf(W1[s * (DV_ + DK_) + DV_ + k], q[k], acc);
    g_qc[c * S_ + s] = acc;
}

// ---------------------------------------------------------------------------
// Main recurrence: one CTA per (batch, slice). State (128 rows x 256 cols fp32)
// lives in registers: thread (ng, dg) owns rows ng*16..+15, cols dg*4..+3.
// Per step: r_partial += w.m ; m = m + w*(a - e*m)   (3 FMA / element)
__global__ void __launch_bounds__(512, 1)
k_main(const int* __restrict__ concepts, const int* __restrict__ interactions,
       const float* __restrict__ vmem) {
    int batch = blockIdx.x >> 2;
    int slice = blockIdx.x & 3;
    int t = threadIdx.x;
    int dg = t & 63, ng = t >> 6;
    int d0 = dg << 2;
    int nbase = slice * RPS_ + ng * 16;

    __shared__ int c_seq[T_];
    __shared__ int i_seq[T_];
    __shared__ __align__(16) float wbuf[2][RPS_];
    __shared__ __align__(16) float ebuf[2][DV_];
    __shared__ __align__(16) float abuf[2][DV_];
    __shared__ __align__(16) float rpart[8][DV_];

    c_seq[t] = concepts[batch * T_ + t];
    i_seq[t] = interactions[batch * T_ + t];

    float4 m[16];
#pragma unroll
    for (int j = 0; j < 16; j++)
        m[j] = *(const float4*)(vmem + (size_t)(nbase + j) * DV_ + d0);

    __syncthreads();
    {   // stage step 0 into buffer 0
        int c0 = c_seq[0], ii = i_seq[0];
        if (t < 128)      { wbuf[0][t] = g_wtab[c0 * N_ + slice * RPS_ + t];
                            abuf[0][128 + t] = g_atab[ii * DV_ + 128 + t]; }
        else if (t < 384)   ebuf[0][t - 128] = g_etab[ii * DV_ + (t - 128)];
        else                abuf[0][t - 384] = g_atab[ii * DV_ + (t - 384)];
    }
    __syncthreads();

    size_t obase = (size_t)batch * T_ * (SLICES_ * DV_) + (size_t)slice * DV_;

    for (int step = 0; step < T_; step++) {
        int cur = step & 1;
        // prefetch next step's tables into registers (latency hidden by FMA loop)
        float p1 = 0.f, p2 = 0.f;
        if (step + 1 < T_) {
            int cn = c_seq[step + 1], in2 = i_seq[step + 1];
            if (t < 128)      { p1 = g_wtab[cn * N_ + slice * RPS_ + t];
                                p2 = g_atab[in2 * DV_ + 128 + t]; }
            else if (t < 384)   p1 = g_etab[in2 * DV_ + (t - 128)];
            else                p1 = g_atab[in2 * DV_ + (t - 384)];
        }
        float4 ev = *(const float4*)&ebuf[cur][d0];
        float4 av = *(const float4*)&abuf[cur][d0];
        float r0 = 0.f, r1 = 0.f, r2 = 0.f, r3 = 0.f;
        const float* wrow = &wbuf[cur][ng * 16];
#pragma unroll
        for (int j = 0; j < 16; j++) {
            float wn = wrow[j];
            float4 mm = m[j];
            r0 = fmaf(wn, mm.x, r0);
            r1 = fmaf(wn, mm.y, r1);
            r2 = fmaf(wn, mm.z, r2);
            r3 = fmaf(wn, mm.w, r3);
            float u0 = fmaf(-ev.x, mm.x, av.x);
            float u1 = fmaf(-ev.y, mm.y, av.y);
            float u2 = fmaf(-ev.z, mm.z, av.z);
            float u3 = fmaf(-ev.w, mm.w, av.w);
            mm.x = fmaf(wn, u0, mm.x);
            mm.y = fmaf(wn, u1, mm.y);
            mm.z = fmaf(wn, u2, mm.z);
            mm.w = fmaf(wn, u3, mm.w);
            m[j] = mm;
        }
        *(float4*)&rpart[ng][d0] = make_float4(r0, r1, r2, r3);
        __syncthreads();
        if (t < 256) {
            float s = rpart[0][t] + rpart[1][t] + rpart[2][t] + rpart[3][t]
                    + rpart[4][t] + rpart[5][t] + rpart[6][t] + rpart[7][t];
            g_rpart[obase + (size_t)step * (SLICES_ * DV_) + t] = s;
        }
        if (step + 1 < T_) {
            int nxt = cur ^ 1;
            if (t < 128)      { wbuf[nxt][t] = p1; abuf[nxt][128 + t] = p2; }
            else if (t < 384)   ebuf[nxt][t - 128] = p1;
            else                abuf[nxt][t - 384] = p1;
        }
        __syncthreads();
    }
}

// ---------------------------------------------------------------------------
// Prediction head: reduce slice partials of r, then 320->64->64->1 MLP.
// 256 threads = 8 warps; each warp processes 2 items at a time (weight LDS reuse).
// Shared: W1r padded 64x260, W2 padded 64x68 (both conflict-free for float4 reads).
__global__ void k_mlp(const int* __restrict__ concepts,
                      const float* __restrict__ W1, const float* __restrict__ W2,
                      const float* __restrict__ b2, const float* __restrict__ W3,
                      const float* __restrict__ b3, float* __restrict__ out) {
    extern __shared__ float sm[];
    float* W1s = sm;                  // 64*260 = 16640
    float* W2s = W1s + 64 * 260;      // 64*68  = 4352
    float* W3s = W2s + 64 * 68;       // 64
    float* b2s = W3s + 64;            // 64
    float* rsm = b2s + 64;            // 16*256 = 4096
    float* h1s = rsm + 16 * 256;      // 16*64  = 1024   (total 26240 floats)
    int tid = threadIdx.x;
    for (int x = tid; x < 64 * 256; x += 256) {
        int s = x >> 8, d = x & 255;
        W1s[s * 260 + d] = W1[s * 320 + d];       // first DV columns of W1
    }
    for (int x = tid; x < 64 * 64; x += 256) {
        int s = x >> 6, k = x & 63;
        W2s[s * 68 + k] = W2[s * 64 + k];
    }
    if (tid < 64) { W3s[tid] = W3[tid]; b2s[tid] = b2[tid]; }
    __syncthreads();

    int w = tid >> 5, lane = tid & 31;
    float b3v = b3[0];
    float4* rA4 = (float4*)(rsm + (w * 2 + 0) * 256);
    float4* rB4 = (float4*)(rsm + (w * 2 + 1) * 256);
    float* h1A = h1s + (w * 2) * 64;
    float* h1B = h1A + 64;
    int pair0 = blockIdx.x * 8 + w;   // 2048 warp-slots, 65536 pairs, 32 iters

    for (int it = 0; it < 32; it++) {
        int pair = pair0 + it * 2048;
        int itemA = pair * 2, itemB = itemA + 1;
        const float4* rpA = (const float4*)(g_rpart + (size_t)itemA * (SLICES_ * DV_));
        const float4* rpB = (const float4*)(g_rpart + (size_t)itemB * (SLICES_ * DV_));
#pragma unroll
        for (int jj = 0; jj < 2; jj++) {
            int p = lane + 32 * jj;   // float4 index 0..63
            float4 a0 = rpA[p], a1 = rpA[64 + p], a2 = rpA[128 + p], a3 = rpA[192 + p];
            rA4[p] = make_float4(a0.x + a1.x + a2.x + a3.x, a0.y + a1.y + a2.y + a3.y,
                                 a0.z + a1.z + a2.z + a3.z, a0.w + a1.w + a2.w + a3.w);
            float4 c0 = rpB[p], c1 = rpB[64 + p], c2 = rpB[128 + p], c3 = rpB[192 + p];
            rB4[p] = make_float4(c0.x + c1.x + c2.x + c3.x, c0.y + c1.y + c2.y + c3.y,
                                 c0.z + c1.z + c2.z + c3.z, c0.w + c1.w + c2.w + c3.w);
        }
        __syncwarp();
        int cA = concepts[itemA];
        int cB = concepts[itemB];
        float acc00 = g_qc[cA * 64 + lane];
        float acc01 = g_qc[cA * 64 + lane + 32];
        float acc10 = g_qc[cB * 64 + lane];
        float acc11 = g_qc[cB * 64 + lane + 32];
#pragma unroll 8
        for (int d4 = 0; d4 < 64; d4++) {
            float4 ra = rA4[d4];
            float4 rb = rB4[d4];
            float4 w0 = *(const float4*)&W1s[lane * 260 + d4 * 4];
            float4 w1 = *(const float4*)&W1s[(lane + 32) * 260 + d4 * 4];
            acc00 += w0.x * ra.x + w0.y * ra.y + w0.z * ra.z + w0.w * ra.w;
            acc10 += w0.x * rb.x + w0.y * rb.y + w0.z * rb.z + w0.w * rb.w;
            acc01 += w1.x * ra.x + w1.y * ra.y + w1.z * ra.z + w1.w * ra.w;
            acc11 += w1.x * rb.x + w1.y * rb.y + w1.z * rb.z + w1.w * rb.w;
        }
        h1A[lane]      = fmaxf(acc00, 0.f);
        h1A[lane + 32] = fmaxf(acc01, 0.f);
        h1B[lane]      = fmaxf(acc10, 0.f);
        h1B[lane + 32] = fmaxf(acc11, 0.f);
        __syncwarp();
        float h2[2][2];
#pragma unroll
        for (int o = 0; o < 2; o++) {
            int s = lane + 32 * o;
            float aA = b2s[s], aB = aA;
#pragma unroll
            for (int k4 = 0; k4 < 16; k4++) {
                float4 wv = *(const float4*)&W2s[s * 68 + k4 * 4];
                float4 ha = *(const float4*)&h1A[k4 * 4];
                float4 hb = *(const float4*)&h1B[k4 * 4];
                aA += wv.x * ha.x + wv.y * ha.y + wv.z * ha.z + wv.w * ha.w;
                aB += wv.x * hb.x + wv.y * hb.y + wv.z * hb.z + wv.w * hb.w;
            }
            h2[0][o] = fmaxf(aA, 0.f);
            h2[1][o] = fmaxf(aB, 0.f);
        }
        float pA = W3s[lane] * h2[0][0] + W3s[lane + 32] * h2[0][1];
        float pB = W3s[lane] * h2[1][0] + W3s[lane + 32] * h2[1][1];
#pragma unroll
        for (int off = 16; off > 0; off >>= 1) {
            pA += __shfl_xor_sync(0xffffffffu, pA, off);
            pB += __shfl_xor_sync(0xffffffffu, pB, off);
        }
        if (lane == 0) {
            out[itemA] = 1.f / (1.f + expf(-(pA + b3v)));
            out[itemB] = 1.f / (1.f + expf(-(pB + b3v)));
        }
        __syncwarp();   // protect rsm/h1s before next iteration overwrites
    }
}

// ---------------------------------------------------------------------------
extern "C" void kernel_launch(void* const* d_in, const int* in_sizes, int n_in,
                              void* d_out, int out_size) {
    const int*   concepts          = (const int*)d_in[0];
    const int*   interactions      = (const int*)d_in[1];
    const float* key_memory        = (const float*)d_in[2];
    const float* value_memory      = (const float*)d_in[3];
    const float* concept_embed     = (const float*)d_in[4];
    const float* interaction_embed = (const float*)d_in[5];
    const float* We = (const float*)d_in[6];
    const float* be = (const float*)d_in[7];
    const float* Wa = (const float*)d_in[8];
    const float* ba = (const float*)d_in[9];
    const float* W1 = (const float*)d_in[10];
    const float* b1 = (const float*)d_in[11];
    const float* W2 = (const float*)d_in[12];
    const float* b2 = (const float*)d_in[13];
    const float* W3 = (const float*)d_in[14];
    const float* b3 = (const float*)d_in[15];
    float* out = (float*)d_out;

    cudaFuncSetAttribute(k_mlp, cudaFuncAttributeMaxDynamicSharedMemorySize, 26240 * 4);

    k_transpose<<<(N_ * DK_) / 256, 256>>>(key_memory);
    k_wtab<<<N_ + 1, 512>>>(concept_embed);
    k_eatab<<<(2 * N_ + 1 + IPB - 1) / IPB, 256>>>(interaction_embed, We, be, Wa, ba);
    k_qc<<<N_ + 1, 64>>>(concept_embed, W1, b1);
    k_main<<<B_ * SLICES_, 512>>>(concepts, interactions, value_memory);
    k_mlp<<<256, 256, 26240 * 4>>>(concepts, W1, W2, b2, W3, b3, out);
}